// round 4
// baseline (speedup 1.0000x reference)
#include <cuda_runtime.h>
#include <cstdint>

// InnerProduct_65429531787441
//   inputs [B,50,64] f32, Theta [128,50] f32
//   proj = einsum("df,bfe->bde"); out[b,d] = sum_e proj^2   -> [B,128] f32
//
// Strategy: per-CTA batched small GEMM in shared memory, all math in packed
// fp32x2 (fma.rn.f32x2, sm_100+) pairing along the D dimension so the Theta
// operand pairs come straight out of an LDS.128 with no repacking.

#define F_DIM 50
#define E_DIM 64
#define D_DIM 128
#define NB    8
#define NTHREADS 256

__device__ __forceinline__ unsigned long long fma2(unsigned long long a,
                                                   unsigned long long b,
                                                   unsigned long long c) {
    unsigned long long d;
    asm("fma.rn.f32x2 %0, %1, %2, %3;" : "=l"(d) : "l"(a), "l"(b), "l"(c));
    return d;
}

__device__ __forceinline__ unsigned long long splat2(float x) {
    unsigned long long d;
    asm("mov.b64 %0, {%1, %1};" : "=l"(d) : "f"(x));
    return d;
}

__global__ void __launch_bounds__(NTHREADS, 3)
innerproduct_kernel(const float* __restrict__ X,
                    const float* __restrict__ Theta,
                    float* __restrict__ out,
                    int Btot) {
    // Static shared: Theta transposed [F][D] (25.6 KB) + one X tile [F][E] (12.8 KB)
    __shared__ float s_theta[F_DIM * D_DIM];
    __shared__ float s_x[F_DIM * E_DIM];

    const int t  = threadIdx.x;
    const int tx = t & 15;        // e-group: 16 groups of 4
    const int ty = t >> 4;        // d-group: 16 groups of 8
    const int e0 = tx * 4;
    const int d0 = ty * 8;

    // Load Theta transposed: s_theta[f*D + d] = Theta[d*F + f]  (one-time, tiny)
    for (int i = t; i < F_DIM * D_DIM; i += NTHREADS) {
        int f = i / D_DIM;
        int d = i - f * D_DIM;
        s_theta[i] = Theta[d * F_DIM + f];
    }

    const int b_begin = (int)blockIdx.x * NB;
    const int b_end   = min(b_begin + NB, Btot);

    for (int b = b_begin; b < b_end; b++) {
        // ---- stage X_b (50x64 f32 = 12.8 KB) into shared via cp.async ----
        {
            const float4* src = reinterpret_cast<const float4*>(
                X + (size_t)b * (F_DIM * E_DIM));
            uint32_t dbase = (uint32_t)__cvta_generic_to_shared(s_x);
            for (int i = t; i < (F_DIM * E_DIM) / 4; i += NTHREADS) {
                asm volatile("cp.async.cg.shared.global [%0], [%1], 16;\n"
                             :: "r"(dbase + i * 16), "l"(src + i));
            }
            asm volatile("cp.async.commit_group;\n"
                         "cp.async.wait_group 0;\n" ::: "memory");
        }
        __syncthreads();  // also covers the Theta fill on the first iteration

        // ---- mainloop: acc[i][j] holds proj for d = d0+2i{,+1}, e = e0+j ----
        unsigned long long acc[4][4];
        #pragma unroll
        for (int i = 0; i < 4; i++)
            #pragma unroll
            for (int j = 0; j < 4; j++) acc[i][j] = 0ull;

        #pragma unroll 5
        for (int f = 0; f < F_DIM; f++) {
            // Theta pairs: LDS.128 -> 2 native f32x2 pairs each, no repack.
            // Per warp: 2 distinct addresses, 16-lane broadcast each.
            ulonglong2 thA = *reinterpret_cast<const ulonglong2*>(
                &s_theta[f * D_DIM + d0]);
            ulonglong2 thB = *reinterpret_cast<const ulonglong2*>(
                &s_theta[f * D_DIM + d0 + 4]);
            // X row: LDS.128, 16 distinct 16B addrs per warp (conflict-free)
            float4 xv = *reinterpret_cast<const float4*>(&s_x[f * E_DIM + e0]);

            unsigned long long th[4] = { thA.x, thA.y, thB.x, thB.y };
            unsigned long long xs[4] = { splat2(xv.x), splat2(xv.y),
                                         splat2(xv.z), splat2(xv.w) };
            #pragma unroll
            for (int i = 0; i < 4; i++)
                #pragma unroll
                for (int j = 0; j < 4; j++)
                    acc[i][j] = fma2(th[i], xs[j], acc[i][j]);
        }

        // ---- epilogue: squared sum over this thread's 4 e's (still packed) ----
        unsigned long long s2[4] = {0ull, 0ull, 0ull, 0ull};
        #pragma unroll
        for (int i = 0; i < 4; i++)
            #pragma unroll
            for (int j = 0; j < 4; j++)
                s2[i] = fma2(acc[i][j], acc[i][j], s2[i]);

        float r[8];
        #pragma unroll
        for (int i = 0; i < 4; i++) {
            float2 v = *reinterpret_cast<float2*>(&s2[i]);
            r[2 * i]     = v.x;   // d0 + 2i
            r[2 * i + 1] = v.y;   // d0 + 2i + 1
        }

        // Reduce across the 16 e-groups. xor distances 1,2,4,8 stay within each
        // 16-lane half of the warp (the two ty groups reduce independently).
        #pragma unroll
        for (int k = 1; k < 16; k <<= 1)
            #pragma unroll
            for (int m = 0; m < 8; m++)
                r[m] += __shfl_xor_sync(0xffffffffu, r[m], k);

        if (tx == 0) {
            float4* o = reinterpret_cast<float4*>(out + (size_t)b * D_DIM + d0);
            o[0] = make_float4(r[0], r[1], r[2], r[3]);
            o[1] = make_float4(r[4], r[5], r[6], r[7]);
        }
        __syncthreads();  // protect s_x before next iteration overwrites it
    }
}

extern "C" void kernel_launch(void* const* d_in, const int* in_sizes, int n_in,
                              void* d_out, int out_size) {
    // Identify inputs vs Theta by size (inputs is ~52.4M elems, Theta 6400).
    int xi = 0, ti = 1;
    if (n_in >= 2 && in_sizes[0] < in_sizes[1]) { xi = 1; ti = 0; }

    const float* X     = (const float*)d_in[xi];
    const float* Theta = (const float*)d_in[ti];
    float*       out   = (float*)d_out;

    int Btot = in_sizes[xi] / (F_DIM * E_DIM);
    int grid = (Btot + NB - 1) / NB;

    innerproduct_kernel<<<grid, NTHREADS>>>(X, Theta, out, Btot);
}

// round 8
// speedup vs baseline: 1.8352x; 1.8352x over previous
#include <cuda_runtime.h>
#include <cuda_bf16.h>
#include <cstdint>

// InnerProduct_65429531787441 — legacy mma.sync (HMMA) bf16-split version.
//   inputs X [B,50,64] f32, Theta [128,50] f32
//   proj = einsum("df,bfe->bde"); out[b,d] = sum_e proj^2 -> [B,128] f32
//
// tcgen05 is unavailable (harness PTX targets compute_103, not 103a), so we
// use mma.sync.aligned.m16n8k16 bf16 (sm_80 baseline PTX, runs on the
// Blackwell tensor pipe as fallback HMMA).
//
// fp32 emulated via bf16 split: D = Ah*Bh + Ah*Bl + Al*Bh  (Al*Bl dropped,
// ~2^-17 relative — far under the 1e-3 gate).
//
// Per batch: C[128,64] = Theta[128,50(pad64)] @ X_b[50,64].
// CTA = 256 threads (8 warps). Warp (mblk = w&3, nh = w>>2) computes the
// M32 x N32 tile [32*mblk, 32*nh]. Theta-hi frags live in registers,
// Theta-lo frags in smem (built once). X streamed with LDG prefetch one
// batch ahead -> register bf16-split -> frag-layout STS (bank == lane on
// both store and load sides). B frag buffers double-buffered.

#define F_DIM 50
#define E_DIM 64
#define D_DIM 128
#define NTHREADS 256
#define GRID 304

struct Smem {
    float    red[2][128];             // cross-warp e-sum reduction
    uint32_t Al[4][2][4][4][32];      // [mblk][mt][ks][reg][lane] Theta-lo frags
    uint32_t BH[2][2048];             // [buf][((ks*8+nt)*2+r)*32+lane] X-hi frags
    uint32_t BL[2][2048];             // X-lo frags
};

__device__ __forceinline__ void mma_bf16(float* c, const uint32_t* a,
                                         uint32_t b0, uint32_t b1) {
    asm("mma.sync.aligned.m16n8k16.row.col.f32.bf16.bf16.f32 "
        "{%0,%1,%2,%3}, {%4,%5,%6,%7}, {%8,%9}, {%0,%1,%2,%3};"
        : "+f"(c[0]), "+f"(c[1]), "+f"(c[2]), "+f"(c[3])
        : "r"(a[0]), "r"(a[1]), "r"(a[2]), "r"(a[3]), "r"(b0), "r"(b1));
}

// Split (v0,v1) into bf16 hi/lo pairs, packed with v0 in the low half.
__device__ __forceinline__ uint32_t split_pack(float v0, float v1,
                                               uint32_t& lo_out) {
    __nv_bfloat16 h0 = __float2bfloat16(v0);
    __nv_bfloat16 h1 = __float2bfloat16(v1);
    __nv_bfloat16 l0 = __float2bfloat16(v0 - __bfloat162float(h0));
    __nv_bfloat16 l1 = __float2bfloat16(v1 - __bfloat162float(h1));
    __nv_bfloat162 hp(h0, h1), lp(l0, l1);
    lo_out = *reinterpret_cast<uint32_t*>(&lp);
    return *reinterpret_cast<uint32_t*>(&hp);
}

__global__ void __launch_bounds__(NTHREADS, 2)
ip_hmma(const float* __restrict__ X, const float* __restrict__ Theta,
        float* __restrict__ out, int Btot) {
    extern __shared__ char smem_raw[];
    Smem& S = *reinterpret_cast<Smem*>(smem_raw);

    const int t    = threadIdx.x;
    const int w    = t >> 5;
    const int l    = t & 31;
    const int mblk = w & 3;     // which 32-row block of D
    const int nh   = w >> 2;    // which 32-col half of E
    const int lg   = l >> 2;    // quad group id (0..7)
    const int la   = l & 3;     // lane in quad

    // ---- Build Theta fragments: hi in registers, lo to shared (once) ----
    uint32_t Ah[2][4][4];       // [mt][ks][reg]
    #pragma unroll
    for (int mt = 0; mt < 2; mt++)
        #pragma unroll
        for (int ks = 0; ks < 4; ks++)
            #pragma unroll
            for (int rg = 0; rg < 4; rg++) {
                int row = mblk * 32 + mt * 16 + lg + ((rg & 1) ? 8 : 0);
                int k   = ks * 16 + la * 2 + ((rg & 2) ? 8 : 0);
                float v0 = (k     < F_DIM) ? Theta[row * F_DIM + k]     : 0.f;
                float v1 = (k + 1 < F_DIM) ? Theta[row * F_DIM + k + 1] : 0.f;
                uint32_t lo;
                Ah[mt][ks][rg] = split_pack(v0, v1, lo);
                if (nh == 0) S.Al[mblk][mt][ks][rg][l] = lo;
            }

    const int stride = (int)gridDim.x;
    const int b0 = (int)blockIdx.x;
    float xr[8][2];   // prefetched X values for this thread's 8 frag slots

    // Each thread owns combos w*8+j, j=0..7 (64 combos = 4ks x 2r x 8nt).
    auto prefetch = [&](int b) {
        const float* Xb = X + (size_t)b * (F_DIM * E_DIM);
        #pragma unroll
        for (int j = 0; j < 8; j++) {
            int combo = w * 8 + j;
            int ks = combo >> 4, r = (combo >> 3) & 1, nt = combo & 7;
            int fp = ks * 8 + r * 4 + la;     // k-pair index, k = 2*fp
            int e  = nt * 8 + lg;
            int f0 = 2 * fp;
            bool ok = (f0 < F_DIM);           // f0 even -> f0+1 <= 49 too
            xr[j][0] = ok ? __ldg(Xb + f0 * E_DIM + e)          : 0.f;
            xr[j][1] = ok ? __ldg(Xb + f0 * E_DIM + E_DIM + e)  : 0.f;
        }
    };
    auto convert = [&](int buf) {
        #pragma unroll
        for (int j = 0; j < 8; j++) {
            int combo = w * 8 + j;
            int ks = combo >> 4, r = (combo >> 3) & 1, nt = combo & 7;
            int idx = ((ks * 8 + nt) * 2 + r) * 32 + l;   // bank == lane
            uint32_t lo;
            uint32_t hi = split_pack(xr[j][0], xr[j][1], lo);
            S.BH[buf][idx] = hi;
            S.BL[buf][idx] = lo;
        }
    };

    if (b0 < Btot) { prefetch(b0); convert(0); }
    __syncthreads();

    int i = 0;
    for (int b = b0; b < Btot; b += stride, i++) {
        const int cur = i & 1;
        const int bn  = b + stride;
        if (bn < Btot) prefetch(bn);   // overlap DRAM with HMMA below

        float C[2][4][4];
        #pragma unroll
        for (int mt = 0; mt < 2; mt++)
            #pragma unroll
            for (int ntl = 0; ntl < 4; ntl++)
                #pragma unroll
                for (int rg = 0; rg < 4; rg++) C[mt][ntl][rg] = 0.f;

        // ---- mainloop: 96 HMMA per warp ----
        #pragma unroll
        for (int ks = 0; ks < 4; ks++) {
            uint32_t Alr[2][4];
            #pragma unroll
            for (int mt = 0; mt < 2; mt++)
                #pragma unroll
                for (int rg = 0; rg < 4; rg++)
                    Alr[mt][rg] = S.Al[mblk][mt][ks][rg][l];
            #pragma unroll
            for (int ntl = 0; ntl < 4; ntl++) {
                int nt = nh * 4 + ntl;
                int bi = ((ks * 8 + nt) * 2) * 32 + l;
                uint32_t b0h = S.BH[cur][bi], b1h = S.BH[cur][bi + 32];
                uint32_t b0l = S.BL[cur][bi], b1l = S.BL[cur][bi + 32];
                #pragma unroll
                for (int mt = 0; mt < 2; mt++) {
                    mma_bf16(C[mt][ntl], Ah[mt][ks], b0h, b1h);  // Ah*Bh
                    mma_bf16(C[mt][ntl], Ah[mt][ks], b0l, b1l);  // Ah*Bl
                    mma_bf16(C[mt][ntl], Alr[mt],    b0h, b1h);  // Al*Bh
                }
            }
        }

        // ---- epilogue: sum_e proj^2 ----
        float s[2][2] = {{0.f, 0.f}, {0.f, 0.f}};   // [mt][row-half]
        #pragma unroll
        for (int mt = 0; mt < 2; mt++)
            #pragma unroll
            for (int ntl = 0; ntl < 4; ntl++) {
                s[mt][0] = fmaf(C[mt][ntl][0], C[mt][ntl][0],
                           fmaf(C[mt][ntl][1], C[mt][ntl][1], s[mt][0]));
                s[mt][1] = fmaf(C[mt][ntl][2], C[mt][ntl][2],
                           fmaf(C[mt][ntl][3], C[mt][ntl][3], s[mt][1]));
            }
        #pragma unroll
        for (int mt = 0; mt < 2; mt++)
            #pragma unroll
            for (int h = 0; h < 2; h++) {
                float v = s[mt][h];
                v += __shfl_xor_sync(0xffffffffu, v, 1);
                v += __shfl_xor_sync(0xffffffffu, v, 2);
                s[mt][h] = v;
            }
        if (la == 0) {
            #pragma unroll
            for (int mt = 0; mt < 2; mt++) {
                S.red[nh][mblk * 32 + mt * 16 + lg]     = s[mt][0];
                S.red[nh][mblk * 32 + mt * 16 + lg + 8] = s[mt][1];
            }
        }
        __syncthreads();
        if (t < D_DIM)
            out[(size_t)b * D_DIM + t] = S.red[0][t] + S.red[1][t];

        if (bn < Btot) convert(cur ^ 1);   // fill other buffer
        __syncthreads();
    }
}

extern "C" void kernel_launch(void* const* d_in, const int* in_sizes, int n_in,
                              void* d_out, int out_size) {
    int xi = 0, ti = 1;
    if (n_in >= 2 && in_sizes[0] < in_sizes[1]) { xi = 1; ti = 0; }

    const float* X     = (const float*)d_in[xi];
    const float* Theta = (const float*)d_in[ti];
    float*       out   = (float*)d_out;
    int Btot = in_sizes[xi] / (F_DIM * E_DIM);

    static int configured = 0;
    (void)configured;
    cudaFuncSetAttribute(ip_hmma, cudaFuncAttributeMaxDynamicSharedMemorySize,
                         (int)sizeof(Smem));
    ip_hmma<<<GRID, NTHREADS, sizeof(Smem)>>>(X, Theta, out, Btot);
}